// round 1
// baseline (speedup 1.0000x reference)
#include <cuda_runtime.h>
#include <math.h>

#define LSEQ 4096
#define DMODEL 1024
#define NHEAD 16
#define DHEAD 64

// Scratch (allocation-free rule: __device__ globals)
__device__ float g_Q[LSEQ * DMODEL];
__device__ float g_K[LSEQ * DMODEL];
__device__ float g_V[LSEQ * DMODEL];   // gated V
__device__ float g_Y[LSEQ * DMODEL];   // attention output (head-interleaved)
__device__ float g_gate[LSEQ];

// ---------------------------------------------------------------------------
// gate[l] = sigmoid((mean(|energy_coeffs[l,:]|) - 0.1) * 10)
// ---------------------------------------------------------------------------
__global__ void gate_kernel(const float* __restrict__ ec, float* __restrict__ gate) {
    int i = blockIdx.x * blockDim.x + threadIdx.x;
    if (i < LSEQ) {
        float s = 0.f;
#pragma unroll
        for (int j = 0; j < 8; j++) s += fabsf(ec[i * 8 + j]);
        float e = s * 0.125f;
        gate[i] = 1.f / (1.f + __expf(-(e - 0.1f) * 10.f));
    }
}

// ---------------------------------------------------------------------------
// SGEMM C[M,N] = A[M,K] @ W[K,N] + bias, with epilogue modes:
//   MODE 0: + bias
//   MODE 1: (acc + bias) * 0.125        (Q projection, folds softmax scale)
//   MODE 2: (acc + bias) * gate[row]    (V projection, folds key gate)
// 128x128x8 tile, 256 threads, 8x8 microtile.
// ---------------------------------------------------------------------------
template <int MODE>
__global__ void __launch_bounds__(256) sgemm_bias(
    const float* __restrict__ A, const float* __restrict__ W,
    const float* __restrict__ bias, float* __restrict__ C,
    int M, int N, int K, const float* __restrict__ gate)
{
    __shared__ float As[8][128];
    __shared__ float Bs[8][128];

    int tid = threadIdx.x;
    int m0 = blockIdx.y * 128;
    int n0 = blockIdx.x * 128;
    int tx = tid & 15;          // 0..15 (n direction)
    int ty = tid >> 4;          // 0..15 (m direction)

    int arow = tid >> 1;        // 0..127
    int acol = (tid & 1) * 4;   // 0 or 4
    int brow = tid >> 5;        // 0..7
    int bcol = (tid & 31) * 4;  // 0..124

    float acc[8][8];
#pragma unroll
    for (int i = 0; i < 8; i++)
#pragma unroll
        for (int j = 0; j < 8; j++) acc[i][j] = 0.f;

    for (int k0 = 0; k0 < K; k0 += 8) {
        float4 av = *(const float4*)&A[(size_t)(m0 + arow) * K + k0 + acol];
        float4 bv = *(const float4*)&W[(size_t)(k0 + brow) * N + n0 + bcol];
        As[acol + 0][arow] = av.x;
        As[acol + 1][arow] = av.y;
        As[acol + 2][arow] = av.z;
        As[acol + 3][arow] = av.w;
        *(float4*)&Bs[brow][bcol] = bv;
        __syncthreads();

#pragma unroll
        for (int k = 0; k < 8; k++) {
            float a[8], b[8];
            *(float4*)&a[0] = *(const float4*)&As[k][ty * 8];
            *(float4*)&a[4] = *(const float4*)&As[k][ty * 8 + 4];
            *(float4*)&b[0] = *(const float4*)&Bs[k][tx * 8];
            *(float4*)&b[4] = *(const float4*)&Bs[k][tx * 8 + 4];
#pragma unroll
            for (int i = 0; i < 8; i++)
#pragma unroll
                for (int j = 0; j < 8; j++) acc[i][j] += a[i] * b[j];
        }
        __syncthreads();
    }

#pragma unroll
    for (int i = 0; i < 8; i++) {
        int r = m0 + ty * 8 + i;
        float g = 1.f;
        if (MODE == 2) g = gate[r];
#pragma unroll
        for (int j = 0; j < 8; j++) {
            int c = n0 + tx * 8 + j;
            float o = acc[i][j] + bias[c];
            if (MODE == 1) o *= 0.125f;
            if (MODE == 2) o *= g;
            C[(size_t)r * N + c] = o;
        }
    }
}

// ---------------------------------------------------------------------------
// Flash attention, fp32. Q already scaled by 1/8, V already gated.
// Grid: (L/64, H). Block: 256 threads = 16(tx:key/dcol) x 16(ty:row).
// Per block: 64 queries of one head; loop over 64 KV tiles of 64 keys.
// Thread microtile: 4 rows x 4 cols.
// ---------------------------------------------------------------------------
#define QS_STRIDE 68
#define KT_STRIDE 68
#define VS_STRIDE 68
#define PS_STRIDE 65
#define ATTN_SMEM ((3 * 64 * 68 + 64 * 65) * 4)

__global__ void __launch_bounds__(256) attn_kernel(
    const float* __restrict__ Q, const float* __restrict__ K,
    const float* __restrict__ V, float* __restrict__ Y)
{
    extern __shared__ float sm[];
    float* Qs = sm;                    // [64][68] row-major over d
    float* Kt = Qs + 64 * QS_STRIDE;   // [64 d][68]  (d-major: Kt[d*68 + key])
    float* Vs = Kt + 64 * KT_STRIDE;   // [64 key][68]
    float* Ps = Vs + 64 * VS_STRIDE;   // [64 row][65]

    int h = blockIdx.y;
    int q0 = blockIdx.x * 64;
    int tid = threadIdx.x;
    int tx = tid & 15;
    int ty = tid >> 4;
    int hoff = h * DHEAD;

    // Load Q tile [64 rows][64 d]
    for (int idx = tid; idx < 64 * 16; idx += 256) {
        int r = idx >> 4;
        int v = (idx & 15) * 4;
        float4 qv = *(const float4*)&Q[(size_t)(q0 + r) * DMODEL + hoff + v];
        *(float4*)&Qs[r * QS_STRIDE + v] = qv;
    }

    float m_i[4], l_i[4], acc[4][4];
#pragma unroll
    for (int i = 0; i < 4; i++) {
        m_i[i] = -1e30f;
        l_i[i] = 0.f;
#pragma unroll
        for (int j = 0; j < 4; j++) acc[i][j] = 0.f;
    }

    for (int kt = 0; kt < LSEQ / 64; kt++) {
        int k0 = kt * 64;
        // Load K (transposed to d-major) and gated V
        for (int idx = tid; idx < 64 * 16; idx += 256) {
            int key = idx >> 4;
            int v = (idx & 15) * 4;
            float4 kv = *(const float4*)&K[(size_t)(k0 + key) * DMODEL + hoff + v];
            Kt[(v + 0) * KT_STRIDE + key] = kv.x;
            Kt[(v + 1) * KT_STRIDE + key] = kv.y;
            Kt[(v + 2) * KT_STRIDE + key] = kv.z;
            Kt[(v + 3) * KT_STRIDE + key] = kv.w;
            float4 vv = *(const float4*)&V[(size_t)(k0 + key) * DMODEL + hoff + v];
            *(float4*)&Vs[key * VS_STRIDE + v] = vv;
        }
        __syncthreads();

        // Scores: s[ii][jj] = Q[row ty*4+ii] . K[key tx*4+jj]   (Q pre-scaled)
        float s[4][4];
#pragma unroll
        for (int i = 0; i < 4; i++)
#pragma unroll
            for (int j = 0; j < 4; j++) s[i][j] = 0.f;

#pragma unroll 16
        for (int d = 0; d < 64; d++) {
            float4 kv = *(const float4*)&Kt[d * KT_STRIDE + tx * 4];
#pragma unroll
            for (int i = 0; i < 4; i++) {
                float qv = Qs[(ty * 4 + i) * QS_STRIDE + d];
                s[i][0] += qv * kv.x;
                s[i][1] += qv * kv.y;
                s[i][2] += qv * kv.z;
                s[i][3] += qv * kv.w;
            }
        }

        // Online softmax update (row reduction across the 16 tx threads)
#pragma unroll
        for (int i = 0; i < 4; i++) {
            float tm = fmaxf(fmaxf(s[i][0], s[i][1]), fmaxf(s[i][2], s[i][3]));
#pragma unroll
            for (int off = 8; off > 0; off >>= 1)
                tm = fmaxf(tm, __shfl_xor_sync(0xffffffffu, tm, off, 16));
            float mnew = fmaxf(m_i[i], tm);
            float scale = __expf(m_i[i] - mnew);
            float rs = 0.f;
#pragma unroll
            for (int j = 0; j < 4; j++) {
                float p = __expf(s[i][j] - mnew);
                Ps[(ty * 4 + i) * PS_STRIDE + tx * 4 + j] = p;
                rs += p;
            }
#pragma unroll
            for (int off = 8; off > 0; off >>= 1)
                rs += __shfl_xor_sync(0xffffffffu, rs, off, 16);
            l_i[i] = l_i[i] * scale + rs;
            m_i[i] = mnew;
#pragma unroll
            for (int j = 0; j < 4; j++) acc[i][j] *= scale;
        }
        __syncthreads();  // Ps visible to all

        // acc += P @ V   (cols tx*4+jj of V)
#pragma unroll 16
        for (int c = 0; c < 64; c++) {
            float4 vv = *(const float4*)&Vs[c * VS_STRIDE + tx * 4];
#pragma unroll
            for (int i = 0; i < 4; i++) {
                float p = Ps[(ty * 4 + i) * PS_STRIDE + c];
                acc[i][0] += p * vv.x;
                acc[i][1] += p * vv.y;
                acc[i][2] += p * vv.z;
                acc[i][3] += p * vv.w;
            }
        }
        __syncthreads();  // before next tile overwrites Kt/Vs/Ps
    }

    // Normalize and write out (head-interleaved [L][D] layout)
#pragma unroll
    for (int i = 0; i < 4; i++) {
        float inv = 1.f / l_i[i];
        int r = q0 + ty * 4 + i;
#pragma unroll
        for (int j = 0; j < 4; j++)
            Y[(size_t)r * DMODEL + hoff + tx * 4 + j] = acc[i][j] * inv;
    }
}

// ---------------------------------------------------------------------------
extern "C" void kernel_launch(void* const* d_in, const int* in_sizes, int n_in,
                              void* d_out, int out_size) {
    const float* q_x = (const float*)d_in[0];
    const float* k_x = (const float*)d_in[1];
    const float* v_x = (const float*)d_in[2];
    const float* ec  = (const float*)d_in[3];
    const float* Wq  = (const float*)d_in[4];
    const float* bq  = (const float*)d_in[5];
    const float* Wk  = (const float*)d_in[6];
    const float* bk  = (const float*)d_in[7];
    const float* Wv  = (const float*)d_in[8];
    const float* bv  = (const float*)d_in[9];
    const float* Wo  = (const float*)d_in[10];
    const float* bo  = (const float*)d_in[11];
    float* out = (float*)d_out;

    float *Qp, *Kp, *Vp, *Yp, *gp;
    cudaGetSymbolAddress((void**)&Qp, g_Q);
    cudaGetSymbolAddress((void**)&Kp, g_K);
    cudaGetSymbolAddress((void**)&Vp, g_V);
    cudaGetSymbolAddress((void**)&Yp, g_Y);
    cudaGetSymbolAddress((void**)&gp, g_gate);

    cudaFuncSetAttribute(attn_kernel,
                         cudaFuncAttributeMaxDynamicSharedMemorySize, ATTN_SMEM);

    gate_kernel<<<(LSEQ + 255) / 256, 256>>>(ec, gp);

    dim3 gemm_grid(DMODEL / 128, LSEQ / 128);
    sgemm_bias<1><<<gemm_grid, 256>>>(q_x, Wq, bq, Qp, LSEQ, DMODEL, DMODEL, nullptr);
    sgemm_bias<0><<<gemm_grid, 256>>>(k_x, Wk, bk, Kp, LSEQ, DMODEL, DMODEL, nullptr);
    sgemm_bias<2><<<gemm_grid, 256>>>(v_x, Wv, bv, Vp, LSEQ, DMODEL, DMODEL, gp);

    attn_kernel<<<dim3(LSEQ / 64, NHEAD), 256, ATTN_SMEM>>>(Qp, Kp, Vp, Yp);

    sgemm_bias<0><<<gemm_grid, 256>>>(Yp, Wo, bo, out, LSEQ, DMODEL, DMODEL, nullptr);
}

// round 3
// speedup vs baseline: 5.6883x; 5.6883x over previous
#include <cuda_runtime.h>
#include <cuda_fp16.h>
#include <stdint.h>
#include <math.h>

#define LSEQ 4096
#define DMODEL 1024
#define NHEAD 16
#define DHEAD 64

// ---------------- scratch (__device__ globals; allocation-free rule) -------
__device__ __half g_xq[LSEQ * DMODEL];
__device__ __half g_xk[LSEQ * DMODEL];
__device__ __half g_xv[LSEQ * DMODEL];
__device__ __half g_Wqt[DMODEL * DMODEL];   // W^T, [n][k]
__device__ __half g_Wkt[DMODEL * DMODEL];
__device__ __half g_Wvt[DMODEL * DMODEL];
__device__ __half g_Wot[DMODEL * DMODEL];
__device__ __half g_Q[LSEQ * DMODEL];       // scaled by 0.125
__device__ __half g_K[LSEQ * DMODEL];
__device__ __half g_Vt[DMODEL * LSEQ];      // gated V, transposed: [head*64+dh][key]
__device__ __half g_Y[LSEQ * DMODEL];       // attention out
__device__ float  g_gate[LSEQ];

// ---------------------------------------------------------------------------
static __device__ __forceinline__ uint32_t packh2(float x, float y) {
    __half2 h = __floats2half2_rn(x, y);
    return *reinterpret_cast<uint32_t*>(&h);
}

static __device__ __forceinline__ void mma16816(float* c, const uint32_t* a,
                                                uint32_t b0, uint32_t b1) {
    asm volatile(
        "mma.sync.aligned.m16n8k16.row.col.f32.f16.f16.f32 "
        "{%0,%1,%2,%3},{%4,%5,%6,%7},{%8,%9},{%0,%1,%2,%3};\n"
        : "+f"(c[0]), "+f"(c[1]), "+f"(c[2]), "+f"(c[3])
        : "r"(a[0]), "r"(a[1]), "r"(a[2]), "r"(a[3]), "r"(b0), "r"(b1));
}

// ---------------------------------------------------------------------------
__global__ void gate_kernel(const float* __restrict__ ec, float* __restrict__ gate) {
    int i = blockIdx.x * blockDim.x + threadIdx.x;
    if (i < LSEQ) {
        float s = 0.f;
#pragma unroll
        for (int j = 0; j < 8; j++) s += fabsf(ec[i * 8 + j]);
        float e = s * 0.125f;
        gate[i] = 1.f / (1.f + __expf(-(e - 0.1f) * 10.f));
    }
}

__global__ void cvt_half4(const float* __restrict__ x, __half* __restrict__ y, int n4) {
    int i = blockIdx.x * blockDim.x + threadIdx.x;
    if (i < n4) {
        float4 v = ((const float4*)x)[i];
        ((__half2*)y)[2 * i]     = __floats2half2_rn(v.x, v.y);
        ((__half2*)y)[2 * i + 1] = __floats2half2_rn(v.z, v.w);
    }
}

// W[K][N] fp32 -> Wt[N][K] half
__global__ void transp_cvt(const float* __restrict__ W, __half* __restrict__ Wt) {
    __shared__ float t[32][33];
    int bx = blockIdx.x * 32, by = blockIdx.y * 32;
    int tx = threadIdx.x, ty = threadIdx.y;  // 32 x 8
#pragma unroll
    for (int i = 0; i < 32; i += 8)
        t[ty + i][tx] = W[(size_t)(by + ty + i) * DMODEL + bx + tx];
    __syncthreads();
#pragma unroll
    for (int i = 0; i < 32; i += 8)
        Wt[(size_t)(bx + ty + i) * DMODEL + by + tx] = __float2half_rn(t[tx][ty + i]);
}

// ---------------------------------------------------------------------------
// fp16 mma GEMM: C[4096,1024] = A[4096,1024] @ Bt^T + bias, epilogue modes:
//  0: float out, +bias              (final O projection -> d_out)
//  1: half out,  (acc+bias)*0.125   (Q)
//  2: half out transposed [col][row], (acc+bias)*gate[row]  (V -> g_Vt)
//  3: half out,  +bias              (K)
// 128x128 block tile, k-chunk 32, 8 warps (2x4), warp tile 64x32.
// ---------------------------------------------------------------------------
#define AS_STRIDE 40

template <int MODE>
__global__ void __launch_bounds__(256) hgemm(
    const __half* __restrict__ A, const __half* __restrict__ Bt,
    const float* __restrict__ bias, float* __restrict__ Cf,
    __half* __restrict__ Ch, const float* __restrict__ gate)
{
    __shared__ __half As[128 * AS_STRIDE];
    __shared__ __half Bs[128 * AS_STRIDE];

    const int tid = threadIdx.x;
    const int m0 = blockIdx.y * 128, n0 = blockIdx.x * 128;
    const int w = tid >> 5, lane = tid & 31;
    const int wm = (w >> 2) * 64, wn = (w & 3) * 32;
    const int g = lane >> 2, j = lane & 3;

    float c[4][4][4];
#pragma unroll
    for (int mf = 0; mf < 4; mf++)
#pragma unroll
        for (int nf = 0; nf < 4; nf++)
#pragma unroll
            for (int r = 0; r < 4; r++) c[mf][nf][r] = 0.f;

    // load chunk 0
    {
        int i = tid;
#pragma unroll
        for (int t = 0; t < 2; t++, i += 256) {
            int r = i >> 2, c8 = (i & 3) * 8;
            *(int4*)&As[r * AS_STRIDE + c8] = *(const int4*)&A[(size_t)(m0 + r) * 1024 + c8];
            *(int4*)&Bs[r * AS_STRIDE + c8] = *(const int4*)&Bt[(size_t)(n0 + r) * 1024 + c8];
        }
    }
    __syncthreads();

    for (int kc = 0; kc < 32; kc++) {
        int4 pa0, pa1, pb0, pb1;
        if (kc < 31) {
            size_t ka = (size_t)(kc + 1) * 32;
            int i = tid, r = i >> 2, c8 = (i & 3) * 8;
            pa0 = *(const int4*)&A[(size_t)(m0 + r) * 1024 + ka + c8];
            pb0 = *(const int4*)&Bt[(size_t)(n0 + r) * 1024 + ka + c8];
            i = tid + 256; r = i >> 2; c8 = (i & 3) * 8;
            pa1 = *(const int4*)&A[(size_t)(m0 + r) * 1024 + ka + c8];
            pb1 = *(const int4*)&Bt[(size_t)(n0 + r) * 1024 + ka + c8];
        }

#pragma unroll
        for (int kk = 0; kk < 32; kk += 16) {
            uint32_t a[4][4], b[4][2];
#pragma unroll
            for (int mf = 0; mf < 4; mf++) {
                const __half* base = &As[(wm + mf * 16 + g) * AS_STRIDE + kk + 2 * j];
                a[mf][0] = *(const uint32_t*)base;
                a[mf][1] = *(const uint32_t*)(base + 8 * AS_STRIDE);
                a[mf][2] = *(const uint32_t*)(base + 8);
                a[mf][3] = *(const uint32_t*)(base + 8 * AS_STRIDE + 8);
            }
#pragma unroll
            for (int nf = 0; nf < 4; nf++) {
                const __half* base = &Bs[(wn + nf * 8 + g) * AS_STRIDE + kk + 2 * j];
                b[nf][0] = *(const uint32_t*)base;
                b[nf][1] = *(const uint32_t*)(base + 8);
            }
#pragma unroll
            for (int mf = 0; mf < 4; mf++)
#pragma unroll
                for (int nf = 0; nf < 4; nf++)
                    mma16816(c[mf][nf], a[mf], b[nf][0], b[nf][1]);
        }
        __syncthreads();
        if (kc < 31) {
            int i = tid, r = i >> 2, c8 = (i & 3) * 8;
            *(int4*)&As[r * AS_STRIDE + c8] = pa0;
            *(int4*)&Bs[r * AS_STRIDE + c8] = pb0;
            i = tid + 256; r = i >> 2; c8 = (i & 3) * 8;
            *(int4*)&As[r * AS_STRIDE + c8] = pa1;
            *(int4*)&Bs[r * AS_STRIDE + c8] = pb1;
        }
        __syncthreads();
    }

    // epilogue
#pragma unroll
    for (int mf = 0; mf < 4; mf++) {
        int row = m0 + wm + mf * 16 + g;
#pragma unroll
        for (int nf = 0; nf < 4; nf++) {
            int col = n0 + wn + nf * 8 + 2 * j;
            float b0 = bias[col], b1 = bias[col + 1];
            float v0 = c[mf][nf][0] + b0, v1 = c[mf][nf][1] + b1;
            float v2 = c[mf][nf][2] + b0, v3 = c[mf][nf][3] + b1;
            if (MODE == 0) {
                Cf[(size_t)row * 1024 + col] = v0;
                Cf[(size_t)row * 1024 + col + 1] = v1;
                Cf[(size_t)(row + 8) * 1024 + col] = v2;
                Cf[(size_t)(row + 8) * 1024 + col + 1] = v3;
            } else if (MODE == 1) {
                *(uint32_t*)&Ch[(size_t)row * 1024 + col] = packh2(v0 * 0.125f, v1 * 0.125f);
                *(uint32_t*)&Ch[(size_t)(row + 8) * 1024 + col] = packh2(v2 * 0.125f, v3 * 0.125f);
            } else if (MODE == 2) {
                float gr = gate[row], gr8 = gate[row + 8];
                Ch[(size_t)col * LSEQ + row]           = __float2half_rn(v0 * gr);
                Ch[(size_t)(col + 1) * LSEQ + row]     = __float2half_rn(v1 * gr);
                Ch[(size_t)col * LSEQ + row + 8]       = __float2half_rn(v2 * gr8);
                Ch[(size_t)(col + 1) * LSEQ + row + 8] = __float2half_rn(v3 * gr8);
            } else {
                *(uint32_t*)&Ch[(size_t)row * 1024 + col] = packh2(v0, v1);
                *(uint32_t*)&Ch[(size_t)(row + 8) * 1024 + col] = packh2(v2, v3);
            }
        }
    }
}

// ---------------------------------------------------------------------------
// fp16 mma flash attention. Q pre-scaled, V pre-gated + pre-transposed.
// Block: 128 queries x one head; 8 warps, each warp owns 16 query rows.
// KV tiles of 64 keys; P stays in registers (mma C layout == A layout).
// ---------------------------------------------------------------------------
#define KS_STRIDE 72

__global__ void __launch_bounds__(256) attn(
    const __half* __restrict__ Q, const __half* __restrict__ K,
    const __half* __restrict__ Vt, __half* __restrict__ Y)
{
    __shared__ __half Ks[64 * KS_STRIDE];   // [key][dh]
    __shared__ __half Vs[64 * KS_STRIDE];   // [dh][key]

    const int h = blockIdx.y, q0 = blockIdx.x * 128;
    const int tid = threadIdx.x, w = tid >> 5, lane = tid & 31;
    const int g = lane >> 2, j = lane & 3;
    const int hoff = h * DHEAD;
    const int row0 = q0 + w * 16 + g;

    // Q fragments in registers (4 k-frags over DH=64)
    uint32_t qa[4][4];
#pragma unroll
    for (int kf = 0; kf < 4; kf++) {
        const __half* qb = &Q[(size_t)row0 * 1024 + hoff + kf * 16 + 2 * j];
        qa[kf][0] = *(const uint32_t*)qb;
        qa[kf][1] = *(const uint32_t*)(qb + 8 * 1024);
        qa[kf][2] = *(const uint32_t*)(qb + 8);
        qa[kf][3] = *(const uint32_t*)(qb + 8 * 1024 + 8);
    }

    float o[8][4];
#pragma unroll
    for (int nf = 0; nf < 8; nf++)
#pragma unroll
        for (int r = 0; r < 4; r++) o[nf][r] = 0.f;
    float m0v = -1e30f, m1v = -1e30f, l0 = 0.f, l1 = 0.f;

    for (int kt = 0; kt < LSEQ / 64; kt++) {
        int k0 = kt * 64;
        {
            int i = tid;
#pragma unroll
            for (int t = 0; t < 2; t++, i += 256) {
                int r = i >> 3, c8 = (i & 7) * 8;
                *(int4*)&Ks[r * KS_STRIDE + c8] =
                    *(const int4*)&K[(size_t)(k0 + r) * 1024 + hoff + c8];
                *(int4*)&Vs[r * KS_STRIDE + c8] =
                    *(const int4*)&Vt[(size_t)(hoff + r) * LSEQ + k0 + c8];
            }
        }
        __syncthreads();

        // S = Q @ K^T (scaled already)
        float s[8][4];
#pragma unroll
        for (int nf = 0; nf < 8; nf++)
#pragma unroll
            for (int r = 0; r < 4; r++) s[nf][r] = 0.f;
#pragma unroll
        for (int kf = 0; kf < 4; kf++)
#pragma unroll
            for (int nf = 0; nf < 8; nf++) {
                const __half* kb = &Ks[(nf * 8 + g) * KS_STRIDE + kf * 16 + 2 * j];
                mma16816(s[nf], qa[kf], *(const uint32_t*)kb, *(const uint32_t*)(kb + 8));
            }

        // online softmax (rows g and g+8; quad = lanes sharing g)
        float mx0 = -1e30f, mx1 = -1e30f;
#pragma unroll
        for (int nf = 0; nf < 8; nf++) {
            mx0 = fmaxf(mx0, fmaxf(s[nf][0], s[nf][1]));
            mx1 = fmaxf(mx1, fmaxf(s[nf][2], s[nf][3]));
        }
        mx0 = fmaxf(mx0, __shfl_xor_sync(0xffffffffu, mx0, 1));
        mx0 = fmaxf(mx0, __shfl_xor_sync(0xffffffffu, mx0, 2));
        mx1 = fmaxf(mx1, __shfl_xor_sync(0xffffffffu, mx1, 1));
        mx1 = fmaxf(mx1, __shfl_xor_sync(0xffffffffu, mx1, 2));
        float mn0 = fmaxf(m0v, mx0), mn1 = fmaxf(m1v, mx1);
        float sc0 = __expf(m0v - mn0), sc1 = __expf(m1v - mn1);

        uint32_t pg[8], pg8[8];
        float rs0 = 0.f, rs1 = 0.f;
#pragma unroll
        for (int nf = 0; nf < 8; nf++) {
            float e0 = __expf(s[nf][0] - mn0), e1 = __expf(s[nf][1] - mn0);
            float e2 = __expf(s[nf][2] - mn1), e3 = __expf(s[nf][3] - mn1);
            rs0 += e0 + e1; rs1 += e2 + e3;
            pg[nf] = packh2(e0, e1);
            pg8[nf] = packh2(e2, e3);
        }
        rs0 += __shfl_xor_sync(0xffffffffu, rs0, 1);
        rs0 += __shfl_xor_sync(0xffffffffu, rs0, 2);
        rs1 += __shfl_xor_sync(0xffffffffu, rs1, 1);
        rs1 += __shfl_xor_sync(0xffffffffu, rs1, 2);
        l0 = l0 * sc0 + rs0; l1 = l1 * sc1 + rs1;
        m0v = mn0; m1v = mn1;
#pragma unroll
        for (int nf = 0; nf < 8; nf++) {
            o[nf][0] *= sc0; o[nf][1] *= sc0;
            o[nf][2] *= sc1; o[nf][3] *= sc1;
        }

        // O += P @ V
#pragma unroll
        for (int kf = 0; kf < 4; kf++) {
            uint32_t a[4] = { pg[2 * kf], pg8[2 * kf], pg[2 * kf + 1], pg8[2 * kf + 1] };
#pragma unroll
            for (int nf = 0; nf < 8; nf++) {
                const __half* vb = &Vs[(nf * 8 + g) * KS_STRIDE + kf * 16 + 2 * j];
                mma16816(o[nf], a, *(const uint32_t*)vb, *(const uint32_t*)(vb + 8));
            }
        }
        __syncthreads();
    }

    float il0 = 1.f / l0, il1 = 1.f / l1;
#pragma unroll
    for (int nf = 0; nf < 8; nf++) {
        int col = hoff + nf * 8 + 2 * j;
        *(uint32_t*)&Y[(size_t)row0 * 1024 + col] = packh2(o[nf][0] * il0, o[nf][1] * il0);
        *(uint32_t*)&Y[(size_t)(row0 + 8) * 1024 + col] = packh2(o[nf][2] * il1, o[nf][3] * il1);
    }
}

// ---------------------------------------------------------------------------
extern "C" void kernel_launch(void* const* d_in, const int* in_sizes, int n_in,
                              void* d_out, int out_size) {
    const float* q_x = (const float*)d_in[0];
    const float* k_x = (const float*)d_in[1];
    const float* v_x = (const float*)d_in[2];
    const float* ec  = (const float*)d_in[3];
    const float* Wq  = (const float*)d_in[4];
    const float* bq  = (const float*)d_in[5];
    const float* Wk  = (const float*)d_in[6];
    const float* bk  = (const float*)d_in[7];
    const float* Wv  = (const float*)d_in[8];
    const float* bv  = (const float*)d_in[9];
    const float* Wo  = (const float*)d_in[10];
    const float* bo  = (const float*)d_in[11];
    float* out = (float*)d_out;

    __half *xq, *xk, *xv, *Wqt, *Wkt, *Wvt, *Wot, *Qh, *Kh, *Vth, *Yh;
    float* gp;
    cudaGetSymbolAddress((void**)&xq, g_xq);
    cudaGetSymbolAddress((void**)&xk, g_xk);
    cudaGetSymbolAddress((void**)&xv, g_xv);
    cudaGetSymbolAddress((void**)&Wqt, g_Wqt);
    cudaGetSymbolAddress((void**)&Wkt, g_Wkt);
    cudaGetSymbolAddress((void**)&Wvt, g_Wvt);
    cudaGetSymbolAddress((void**)&Wot, g_Wot);
    cudaGetSymbolAddress((void**)&Qh, g_Q);
    cudaGetSymbolAddress((void**)&Kh, g_K);
    cudaGetSymbolAddress((void**)&Vth, g_Vt);
    cudaGetSymbolAddress((void**)&Yh, g_Y);
    cudaGetSymbolAddress((void**)&gp, g_gate);

    gate_kernel<<<(LSEQ + 255) / 256, 256>>>(ec, gp);

    int n4 = LSEQ * DMODEL / 4;
    cvt_half4<<<(n4 + 255) / 256, 256>>>(q_x, xq, n4);
    cvt_half4<<<(n4 + 255) / 256, 256>>>(k_x, xk, n4);
    cvt_half4<<<(n4 + 255) / 256, 256>>>(v_x, xv, n4);

    dim3 tb(32, 8), tg(DMODEL / 32, DMODEL / 32);
    transp_cvt<<<tg, tb>>>(Wq, Wqt);
    transp_cvt<<<tg, tb>>>(Wk, Wkt);
    transp_cvt<<<tg, tb>>>(Wv, Wvt);
    transp_cvt<<<tg, tb>>>(Wo, Wot);

    dim3 gg(DMODEL / 128, LSEQ / 128);
    hgemm<1><<<gg, 256>>>(xq, Wqt, bq, nullptr, Qh, nullptr);
    hgemm<3><<<gg, 256>>>(xk, Wkt, bk, nullptr, Kh, nullptr);
    hgemm<2><<<gg, 256>>>(xv, Wvt, bv, nullptr, Vth, gp);

    attn<<<dim3(LSEQ / 128, NHEAD), 256>>>(Qh, Kh, Vth, Yh);

    hgemm<0><<<gg, 256>>>(Yh, Wot, bo, out, nullptr, nullptr);
}

// round 4
// speedup vs baseline: 6.2528x; 1.0993x over previous
#include <cuda_runtime.h>
#include <cuda_fp16.h>
#include <stdint.h>
#include <math.h>

#define LSEQ 4096
#define DMODEL 1024
#define NHEAD 16
#define DHEAD 64

// ---------------- scratch (__device__ globals; allocation-free rule) -------
__device__ __half g_xq[LSEQ * DMODEL];
__device__ __half g_xk[LSEQ * DMODEL];
__device__ __half g_xv[LSEQ * DMODEL];
__device__ __half g_Wqt[DMODEL * DMODEL];   // W^T, [n][k]
__device__ __half g_Wkt[DMODEL * DMODEL];
__device__ __half g_Wvt[DMODEL * DMODEL];
__device__ __half g_Wot[DMODEL * DMODEL];
__device__ __half g_Q[LSEQ * DMODEL];       // scaled by 0.125*log2(e)
__device__ __half g_K[LSEQ * DMODEL];
__device__ __half g_Vt[DMODEL * LSEQ];      // gated V, transposed: [head*64+dh][key]
__device__ __half g_Y[LSEQ * DMODEL];       // attention out
__device__ float  g_gate[LSEQ];

#define QSCALE (0.125f * 1.4426950408889634f)   // 1/sqrt(64) * log2(e)

// ---------------------------------------------------------------------------
static __device__ __forceinline__ uint32_t packh2(float x, float y) {
    __half2 h = __floats2half2_rn(x, y);
    return *reinterpret_cast<uint32_t*>(&h);
}

static __device__ __forceinline__ void mma16816(float* c, const uint32_t* a,
                                                uint32_t b0, uint32_t b1) {
    asm volatile(
        "mma.sync.aligned.m16n8k16.row.col.f32.f16.f16.f32 "
        "{%0,%1,%2,%3},{%4,%5,%6,%7},{%8,%9},{%0,%1,%2,%3};\n"
        : "+f"(c[0]), "+f"(c[1]), "+f"(c[2]), "+f"(c[3])
        : "r"(a[0]), "r"(a[1]), "r"(a[2]), "r"(a[3]), "r"(b0), "r"(b1));
}

static __device__ __forceinline__ void cp16(void* smem, const void* gmem) {
    uint32_t s = (uint32_t)__cvta_generic_to_shared(smem);
    asm volatile("cp.async.cg.shared.global [%0], [%1], 16;\n" :: "r"(s), "l"(gmem));
}
static __device__ __forceinline__ void cp_commit() {
    asm volatile("cp.async.commit_group;\n");
}
static __device__ __forceinline__ void cp_wait0() {
    asm volatile("cp.async.wait_group 0;\n");
}

// ---------------------------------------------------------------------------
__global__ void gate_kernel(const float* __restrict__ ec, float* __restrict__ gate) {
    int i = blockIdx.x * blockDim.x + threadIdx.x;
    if (i < LSEQ) {
        float s = 0.f;
#pragma unroll
        for (int j = 0; j < 8; j++) s += fabsf(ec[i * 8 + j]);
        float e = s * 0.125f;
        gate[i] = 1.f / (1.f + __expf(-(e - 0.1f) * 10.f));
    }
}

__global__ void cvt_half4(const float* __restrict__ x, __half* __restrict__ y, int n4) {
    int i = blockIdx.x * blockDim.x + threadIdx.x;
    if (i < n4) {
        float4 v = ((const float4*)x)[i];
        ((__half2*)y)[2 * i]     = __floats2half2_rn(v.x, v.y);
        ((__half2*)y)[2 * i + 1] = __floats2half2_rn(v.z, v.w);
    }
}

// W[K][N] fp32 -> Wt[N][K] half
__global__ void transp_cvt(const float* __restrict__ W, __half* __restrict__ Wt) {
    __shared__ float t[32][33];
    int bx = blockIdx.x * 32, by = blockIdx.y * 32;
    int tx = threadIdx.x, ty = threadIdx.y;  // 32 x 8
#pragma unroll
    for (int i = 0; i < 32; i += 8)
        t[ty + i][tx] = W[(size_t)(by + ty + i) * DMODEL + bx + tx];
    __syncthreads();
#pragma unroll
    for (int i = 0; i < 32; i += 8)
        Wt[(size_t)(bx + ty + i) * DMODEL + by + tx] = __float2half_rn(t[tx][ty + i]);
}

// ---------------------------------------------------------------------------
// fp16 mma GEMM with cp.async 2-stage pipeline.
//  MODE 0: float out, +bias              (final O projection -> d_out)
//  MODE 1: half out,  (acc+bias)*QSCALE  (Q)
//  MODE 2: half out transposed [col][row], (acc+bias)*gate[row]  (V -> g_Vt)
//  MODE 3: half out,  +bias              (K)
// 128x128 block tile, k-chunk 32, 8 warps (2x4), warp tile 64x32.
// ---------------------------------------------------------------------------
#define AS_STRIDE 40

template <int MODE>
__global__ void __launch_bounds__(256) hgemm(
    const __half* __restrict__ A, const __half* __restrict__ Bt,
    const float* __restrict__ bias, float* __restrict__ Cf,
    __half* __restrict__ Ch, const float* __restrict__ gate)
{
    __shared__ __half As[2][128 * AS_STRIDE];
    __shared__ __half Bs[2][128 * AS_STRIDE];

    const int tid = threadIdx.x;
    const int m0 = blockIdx.y * 128, n0 = blockIdx.x * 128;
    const int w = tid >> 5, lane = tid & 31;
    const int wm = (w >> 2) * 64, wn = (w & 3) * 32;
    const int g = lane >> 2, j = lane & 3;

    // per-thread load coords: 512 16B-chunks per tile (128 rows x 4 chunks)
    const int lr0 = tid >> 1,          lc0 = (tid & 1) * 16;        // chunks 0..255
    const int lr1 = (tid + 256) >> 1,  lc1 = ((tid + 256) & 1) * 16; // chunks 256..511
    // (each row is 32 halves = 2 chunks of 16 halves? no: 32 halves = 64B = 4x16B)
    // simpler mapping: i in [0,512): r=i>>2, c=(i&3)*8 halves
    float c[4][4][4];
#pragma unroll
    for (int mf = 0; mf < 4; mf++)
#pragma unroll
        for (int nf = 0; nf < 4; nf++)
#pragma unroll
            for (int r = 0; r < 4; r++) c[mf][nf][r] = 0.f;

    (void)lr0; (void)lc0; (void)lr1; (void)lc1;

    // prologue: stage 0
    {
        int i = tid;
#pragma unroll
        for (int t = 0; t < 2; t++, i += 256) {
            int r = i >> 2, c8 = (i & 3) * 8;
            cp16(&As[0][r * AS_STRIDE + c8], &A[(size_t)(m0 + r) * 1024 + c8]);
            cp16(&Bs[0][r * AS_STRIDE + c8], &Bt[(size_t)(n0 + r) * 1024 + c8]);
        }
        cp_commit();
    }

    for (int kc = 0; kc < 32; kc++) {
        cp_wait0();
        __syncthreads();
        if (kc < 31) {
            size_t ka = (size_t)(kc + 1) * 32;
            int nb = (kc + 1) & 1;
            int i = tid;
#pragma unroll
            for (int t = 0; t < 2; t++, i += 256) {
                int r = i >> 2, c8 = (i & 3) * 8;
                cp16(&As[nb][r * AS_STRIDE + c8], &A[(size_t)(m0 + r) * 1024 + ka + c8]);
                cp16(&Bs[nb][r * AS_STRIDE + c8], &Bt[(size_t)(n0 + r) * 1024 + ka + c8]);
            }
            cp_commit();
        }
        const __half* as = As[kc & 1];
        const __half* bs = Bs[kc & 1];

#pragma unroll
        for (int kk = 0; kk < 32; kk += 16) {
            uint32_t a[4][4], b[4][2];
#pragma unroll
            for (int mf = 0; mf < 4; mf++) {
                const __half* base = &as[(wm + mf * 16 + g) * AS_STRIDE + kk + 2 * j];
                a[mf][0] = *(const uint32_t*)base;
                a[mf][1] = *(const uint32_t*)(base + 8 * AS_STRIDE);
                a[mf][2] = *(const uint32_t*)(base + 8);
                a[mf][3] = *(const uint32_t*)(base + 8 * AS_STRIDE + 8);
            }
#pragma unroll
            for (int nf = 0; nf < 4; nf++) {
                const __half* base = &bs[(wn + nf * 8 + g) * AS_STRIDE + kk + 2 * j];
                b[nf][0] = *(const uint32_t*)base;
                b[nf][1] = *(const uint32_t*)(base + 8);
            }
#pragma unroll
            for (int mf = 0; mf < 4; mf++)
#pragma unroll
                for (int nf = 0; nf < 4; nf++)
                    mma16816(c[mf][nf], a[mf], b[nf][0], b[nf][1]);
        }
    }

    // epilogue
#pragma unroll
    for (int mf = 0; mf < 4; mf++) {
        int row = m0 + wm + mf * 16 + g;
#pragma unroll
        for (int nf = 0; nf < 4; nf++) {
            int col = n0 + wn + nf * 8 + 2 * j;
            float b0 = bias[col], b1 = bias[col + 1];
            float v0 = c[mf][nf][0] + b0, v1 = c[mf][nf][1] + b1;
            float v2 = c[mf][nf][2] + b0, v3 = c[mf][nf][3] + b1;
            if (MODE == 0) {
                Cf[(size_t)row * 1024 + col] = v0;
                Cf[(size_t)row * 1024 + col + 1] = v1;
                Cf[(size_t)(row + 8) * 1024 + col] = v2;
                Cf[(size_t)(row + 8) * 1024 + col + 1] = v3;
            } else if (MODE == 1) {
                *(uint32_t*)&Ch[(size_t)row * 1024 + col] = packh2(v0 * QSCALE, v1 * QSCALE);
                *(uint32_t*)&Ch[(size_t)(row + 8) * 1024 + col] = packh2(v2 * QSCALE, v3 * QSCALE);
            } else if (MODE == 2) {
                float gr = gate[row], gr8 = gate[row + 8];
                Ch[(size_t)col * LSEQ + row]           = __float2half_rn(v0 * gr);
                Ch[(size_t)(col + 1) * LSEQ + row]     = __float2half_rn(v1 * gr);
                Ch[(size_t)col * LSEQ + row + 8]       = __float2half_rn(v2 * gr8);
                Ch[(size_t)(col + 1) * LSEQ + row + 8] = __float2half_rn(v3 * gr8);
            } else {
                *(uint32_t*)&Ch[(size_t)row * 1024 + col] = packh2(v0, v1);
                *(uint32_t*)&Ch[(size_t)(row + 8) * 1024 + col] = packh2(v2, v3);
            }
        }
    }
}

// ---------------------------------------------------------------------------
// fp16 mma flash attention, cp.async 2-stage KV pipeline.
// Q pre-scaled by 1/8*log2e (scores in log2 domain -> exp2f softmax).
// Block: 128 queries x one head; 8 warps, each warp owns 16 query rows.
// ---------------------------------------------------------------------------
#define KS_STRIDE 72

__global__ void __launch_bounds__(256) attn(
    const __half* __restrict__ Q, const __half* __restrict__ K,
    const __half* __restrict__ Vt, __half* __restrict__ Y)
{
    __shared__ __half Ks[2][64 * KS_STRIDE];   // [key][dh]
    __shared__ __half Vs[2][64 * KS_STRIDE];   // [dh][key]

    const int h = blockIdx.y, q0 = blockIdx.x * 128;
    const int tid = threadIdx.x, w = tid >> 5, lane = tid & 31;
    const int g = lane >> 2, j = lane & 3;
    const int hoff = h * DHEAD;
    const int row0 = q0 + w * 16 + g;

    // Q fragments in registers (4 k-frags over DH=64)
    uint32_t qa[4][4];
#pragma unroll
    for (int kf = 0; kf < 4; kf++) {
        const __half* qb = &Q[(size_t)row0 * 1024 + hoff + kf * 16 + 2 * j];
        qa[kf][0] = *(const uint32_t*)qb;
        qa[kf][1] = *(const uint32_t*)(qb + 8 * 1024);
        qa[kf][2] = *(const uint32_t*)(qb + 8);
        qa[kf][3] = *(const uint32_t*)(qb + 8 * 1024 + 8);
    }

    float o[8][4];
#pragma unroll
    for (int nf = 0; nf < 8; nf++)
#pragma unroll
        for (int r = 0; r < 4; r++) o[nf][r] = 0.f;
    float m0v = -1e30f, m1v = -1e30f, l0 = 0.f, l1 = 0.f;

    // prologue: stage 0 (tile 0)
    {
        int i = tid;
#pragma unroll
        for (int t = 0; t < 2; t++, i += 256) {
            int r = i >> 3, c8 = (i & 7) * 8;
            cp16(&Ks[0][r * KS_STRIDE + c8], &K[(size_t)r * 1024 + hoff + c8]);
            cp16(&Vs[0][r * KS_STRIDE + c8], &Vt[(size_t)(hoff + r) * LSEQ + c8]);
        }
        cp_commit();
    }

    for (int kt = 0; kt < LSEQ / 64; kt++) {
        cp_wait0();
        __syncthreads();
        if (kt < LSEQ / 64 - 1) {
            int k0n = (kt + 1) * 64;
            int nb = (kt + 1) & 1;
            int i = tid;
#pragma unroll
            for (int t = 0; t < 2; t++, i += 256) {
                int r = i >> 3, c8 = (i & 7) * 8;
                cp16(&Ks[nb][r * KS_STRIDE + c8],
                     &K[(size_t)(k0n + r) * 1024 + hoff + c8]);
                cp16(&Vs[nb][r * KS_STRIDE + c8],
                     &Vt[(size_t)(hoff + r) * LSEQ + k0n + c8]);
            }
            cp_commit();
        }
        const __half* ks = Ks[kt & 1];
        const __half* vs = Vs[kt & 1];

        // S = Q @ K^T  (log2-domain, scale folded into Q)
        float s[8][4];
#pragma unroll
        for (int nf = 0; nf < 8; nf++)
#pragma unroll
            for (int r = 0; r < 4; r++) s[nf][r] = 0.f;
#pragma unroll
        for (int kf = 0; kf < 4; kf++)
#pragma unroll
            for (int nf = 0; nf < 8; nf++) {
                const __half* kb = &ks[(nf * 8 + g) * KS_STRIDE + kf * 16 + 2 * j];
                mma16816(s[nf], qa[kf], *(const uint32_t*)kb, *(const uint32_t*)(kb + 8));
            }

        // online softmax (rows g and g+8; quad = lanes sharing g)
        float mx0 = -1e30f, mx1 = -1e30f;
#pragma unroll
        for (int nf = 0; nf < 8; nf++) {
            mx0 = fmaxf(mx0, fmaxf(s[nf][0], s[nf][1]));
            mx1 = fmaxf(mx1, fmaxf(s[nf][2], s[nf][3]));
        }
        mx0 = fmaxf(mx0, __shfl_xor_sync(0xffffffffu, mx0, 1));
        mx0 = fmaxf(mx0, __shfl_xor_sync(0xffffffffu, mx0, 2));
        mx1 = fmaxf(mx1, __shfl_xor_sync(0xffffffffu, mx1, 1));
        mx1 = fmaxf(mx1, __shfl_xor_sync(0xffffffffu, mx1, 2));
        float mn0 = fmaxf(m0v, mx0), mn1 = fmaxf(m1v, mx1);
        float sc0 = exp2f(m0v - mn0), sc1 = exp2f(m1v - mn1);

        uint32_t pg[8], pg8[8];
        float rs0 = 0.f, rs1 = 0.f;
#pragma unroll
        for (int nf = 0; nf < 8; nf++) {
            float e0 = exp2f(s[nf][0] - mn0), e1 = exp2f(s[nf][1] - mn0);
            float e2 = exp2f(s[nf][2] - mn1), e3 = exp2f(s[nf][3] - mn1);
            rs0 += e0 + e1; rs1 += e2 + e3;
            pg[nf] = packh2(e0, e1);
            pg8[nf] = packh2(e2, e3);
        }
        rs0 += __shfl_xor_sync(0xffffffffu, rs0, 1);
        rs0 += __shfl_xor_sync(0xffffffffu, rs0, 2);
        rs1 += __shfl_xor_sync(0xffffffffu, rs1, 1);
        rs1 += __shfl_xor_sync(0xffffffffu, rs1, 2);
        l0 = l0 * sc0 + rs0; l1 = l1 * sc1 + rs1;
        m0v = mn0; m1v = mn1;
#pragma unroll
        for (int nf = 0; nf < 8; nf++) {
            o[nf][0] *= sc0; o[nf][1] *= sc0;
            o[nf][2] *= sc1; o[nf][3] *= sc1;
        }

        // O += P @ V
#pragma unroll
        for (int kf = 0; kf < 4; kf++) {
            uint32_t a[4] = { pg[2 * kf], pg8[2 * kf], pg[2 * kf + 1], pg8[2 * kf + 1] };
#pragma unroll
            for (int nf = 0; nf < 8; nf++) {
                const __half* vb = &vs[(nf * 8 + g) * KS_STRIDE + kf * 16 + 2 * j];
                mma16816(o[nf], a, *(const uint32_t*)vb, *(const uint32_t*)(vb + 8));
            }
        }
        __syncthreads();
    }

    float il0 = 1.f / l0, il1 = 1.f / l1;
#pragma unroll
    for (int nf = 0; nf < 8; nf++) {
        int col = hoff + nf * 8 + 2 * j;
        *(uint32_t*)&Y[(size_t)row0 * 1024 + col] = packh2(o[nf][0] * il0, o[nf][1] * il0);
        *(uint32_t*)&Y[(size_t)(row0 + 8) * 1024 + col] = packh2(o[nf][2] * il1, o[nf][3] * il1);
    }
}

// ---------------------------------------------------------------------------
extern "C" void kernel_launch(void* const* d_in, const int* in_sizes, int n_in,
                              void* d_out, int out_size) {
    const float* q_x = (const float*)d_in[0];
    const float* k_x = (const float*)d_in[1];
    const float* v_x = (const float*)d_in[2];
    const float* ec  = (const float*)d_in[3];
    const float* Wq  = (const float*)d_in[4];
    const float* bq  = (const float*)d_in[5];
    const float* Wk  = (const float*)d_in[6];
    const float* bk  = (const float*)d_in[7];
    const float* Wv  = (const float*)d_in[8];
    const float* bv  = (const float*)d_in[9];
    const float* Wo  = (const float*)d_in[10];
    const float* bo  = (const float*)d_in[11];
    float* out = (float*)d_out;

    __half *xq, *xk, *xv, *Wqt, *Wkt, *Wvt, *Wot, *Qh, *Kh, *Vth, *Yh;
    float* gp;
    cudaGetSymbolAddress((void**)&xq, g_xq);
    cudaGetSymbolAddress((void**)&xk, g_xk);
    cudaGetSymbolAddress((void**)&xv, g_xv);
    cudaGetSymbolAddress((void**)&Wqt, g_Wqt);
    cudaGetSymbolAddress((void**)&Wkt, g_Wkt);
    cudaGetSymbolAddress((void**)&Wvt, g_Wvt);
    cudaGetSymbolAddress((void**)&Wot, g_Wot);
    cudaGetSymbolAddress((void**)&Qh, g_Q);
    cudaGetSymbolAddress((void**)&Kh, g_K);
    cudaGetSymbolAddress((void**)&Vth, g_Vt);
    cudaGetSymbolAddress((void**)&Yh, g_Y);
    cudaGetSymbolAddress((void**)&gp, g_gate);

    gate_kernel<<<(LSEQ + 255) / 256, 256>>>(ec, gp);

    int n4 = LSEQ * DMODEL / 4;
    cvt_half4<<<(n4 + 255) / 256, 256>>>(q_x, xq, n4);
    cvt_half4<<<(n4 + 255) / 256, 256>>>(k_x, xk, n4);
    cvt_half4<<<(n4 + 255) / 256, 256>>>(v_x, xv, n4);

    dim3 tb(32, 8), tg(DMODEL / 32, DMODEL / 32);
    transp_cvt<<<tg, tb>>>(Wq, Wqt);
    transp_cvt<<<tg, tb>>>(Wk, Wkt);
    transp_cvt<<<tg, tb>>>(Wv, Wvt);
    transp_cvt<<<tg, tb>>>(Wo, Wot);

    dim3 gg(DMODEL / 128, LSEQ / 128);
    hgemm<1><<<gg, 256>>>(xq, Wqt, bq, nullptr, Qh, nullptr);
    hgemm<3><<<gg, 256>>>(xk, Wkt, bk, nullptr, Kh, nullptr);
    hgemm<2><<<gg, 256>>>(xv, Wvt, bv, nullptr, Vth, gp);

    attn<<<dim3(LSEQ / 128, NHEAD), 256>>>(Qh, Kh, Vth, Yh);

    hgemm<0><<<gg, 256>>>(Yh, Wot, bo, out, nullptr, nullptr);
}